// round 1
// baseline (speedup 1.0000x reference)
#include <cuda_runtime.h>
#include <mma.h>
#include <cstdint>

using namespace nvcuda;

#define HIDDEN 2048
#define NHEADS 16
#define HDIM   128
#define BATCH  2
#define SEQ    2048
#define TOKENS (BATCH * SEQ)     // 4096
#define QKV_N  (3 * HIDDEN)      // 6144

// Scratch (allocation-free rule: __device__ globals)
__device__ float g_qkv[(size_t)TOKENS * QKV_N];   // 96 MB
__device__ float g_ctx[(size_t)TOKENS * HIDDEN];  // 32 MB

__device__ __forceinline__ float to_tf32(float x) {
    uint32_t u;
    asm("cvt.rna.tf32.f32 %0, %1;" : "=r"(u) : "f"(x));
    return __uint_as_float(u);
}

__device__ __forceinline__ void mma_m16n8k8(float& c0, float& c1, float& c2, float& c3,
                                            uint32_t a0, uint32_t a1, uint32_t a2, uint32_t a3,
                                            uint32_t b0, uint32_t b1) {
    asm volatile(
        "mma.sync.aligned.m16n8k8.row.col.f32.tf32.tf32.f32 "
        "{%0,%1,%2,%3}, {%4,%5,%6,%7}, {%8,%9}, {%0,%1,%2,%3};\n"
        : "+f"(c0), "+f"(c1), "+f"(c2), "+f"(c3)
        : "r"(a0), "r"(a1), "r"(a2), "r"(a3), "r"(b0), "r"(b1));
}

// ============================================================================
// Generic TF32 GEMM with fused bias: C[M,N] = A[M,K] @ B[K,N] + bias[N]
// Block tile 128x128, BK=16, 8 warps (2x4), warp tile 64x32 via wmma m16n16k8.
// Bias is pre-loaded into the accumulator fragments from a replicated smem tile.
// ============================================================================
#define BM 128
#define BN 128
#define BKK 16

__global__ __launch_bounds__(256) void gemm_bias_tf32(
    const float* __restrict__ A, const float* __restrict__ B,
    const float* __restrict__ bias, float* __restrict__ C,
    int M, int N, int K)
{
    __shared__ float As[BM][BKK + 4];     // 128 x 20
    __shared__ float Bs[BKK][BN + 4];     // 16 x 132
    __shared__ float Brep[16][BN + 4];    // bias replicated over 16 rows

    const int tid  = threadIdx.x;
    const int warp = tid >> 5;
    const int wr   = warp >> 2;   // 0..1
    const int wc   = warp & 3;    // 0..3
    const int row0 = blockIdx.y * BM;
    const int col0 = blockIdx.x * BN;

    for (int i = tid; i < 16 * BN; i += 256) {
        int r = i / BN, c = i % BN;
        Brep[r][c] = bias[col0 + c];
    }
    __syncthreads();

    wmma::fragment<wmma::accumulator, 16, 16, 8, float> acc[4][2];
#pragma unroll
    for (int i = 0; i < 4; i++)
#pragma unroll
        for (int j = 0; j < 2; j++)
            wmma::load_matrix_sync(acc[i][j], &Brep[0][wc * 32 + j * 16], BN + 4,
                                   wmma::mem_row_major);
    __syncthreads();

    for (int k0 = 0; k0 < K; k0 += BKK) {
        // A tile: 128 x 16
        for (int i = tid; i < BM * BKK / 4; i += 256) {
            int f = i * 4;
            int r = f / BKK, c = f % BKK;
            float4 v = *reinterpret_cast<const float4*>(&A[(size_t)(row0 + r) * K + k0 + c]);
            As[r][c]     = to_tf32(v.x);
            As[r][c + 1] = to_tf32(v.y);
            As[r][c + 2] = to_tf32(v.z);
            As[r][c + 3] = to_tf32(v.w);
        }
        // B tile: 16 x 128
        for (int i = tid; i < BKK * BN / 4; i += 256) {
            int f = i * 4;
            int r = f / BN, c = f % BN;
            float4 v = *reinterpret_cast<const float4*>(&B[(size_t)(k0 + r) * N + col0 + c]);
            Bs[r][c]     = to_tf32(v.x);
            Bs[r][c + 1] = to_tf32(v.y);
            Bs[r][c + 2] = to_tf32(v.z);
            Bs[r][c + 3] = to_tf32(v.w);
        }
        __syncthreads();

#pragma unroll
        for (int kk = 0; kk < BKK; kk += 8) {
            wmma::fragment<wmma::matrix_a, 16, 16, 8, wmma::precision::tf32, wmma::row_major> fa[4];
            wmma::fragment<wmma::matrix_b, 16, 16, 8, wmma::precision::tf32, wmma::row_major> fb[2];
#pragma unroll
            for (int i = 0; i < 4; i++)
                wmma::load_matrix_sync(fa[i], &As[wr * 64 + i * 16][kk], BKK + 4);
#pragma unroll
            for (int j = 0; j < 2; j++)
                wmma::load_matrix_sync(fb[j], &Bs[kk][wc * 32 + j * 16], BN + 4);
#pragma unroll
            for (int i = 0; i < 4; i++)
#pragma unroll
                for (int j = 0; j < 2; j++)
                    wmma::mma_sync(acc[i][j], fa[i], fb[j], acc[i][j]);
        }
        __syncthreads();
    }

#pragma unroll
    for (int i = 0; i < 4; i++)
#pragma unroll
        for (int j = 0; j < 2; j++)
            wmma::store_matrix_sync(
                &C[(size_t)(row0 + wr * 64 + i * 16) * N + col0 + wc * 32 + j * 16],
                acc[i][j], N, wmma::mem_row_major);
}

// ============================================================================
// Flash attention (TF32 mma.sync), Q-tile = 64, K-tile = 64, d = 128.
// grid = (SEQ/64, BATCH*NHEADS), 256 threads (8 warps).
// Scores partition:  warp = (wq=warp>>1) x (wh=warp&1): 16 q-rows x 32 k-cols
// PV partition:      same wq, wh selects d-half: 16 q-rows x 64 d-cols
// Online softmax via known m16n8k8 accumulator row layout.
// ============================================================================
#define QT  64
#define KT  64
#define QLD 132   // pad: conflict-free frag loads
#define PLD 68

__global__ __launch_bounds__(256) void attn_tf32(
    const float* __restrict__ qkv, const float* __restrict__ mask,
    float* __restrict__ ctx)
{
    extern __shared__ float sm[];
    float* Qs    = sm;                  // QT x QLD
    float* KVs   = Qs + QT * QLD;       // KT x QLD (K then V, reused)
    float* Ps    = KVs + KT * QLD;      // QT x PLD (scores -> probs)
    float* row_m = Ps + QT * PLD;       // QT
    float* row_l = row_m + QT;          // QT
    float* row_c = row_l + QT;          // QT

    const int tid  = threadIdx.x;
    const int warp = tid >> 5, lane = tid & 31;
    const int wq = warp >> 1, wh = warp & 1;
    const int lr = lane >> 2, lc = lane & 3;
    const int b  = blockIdx.y >> 4, h = blockIdx.y & 15;
    const int q0 = blockIdx.x * QT;
    const int tokb = b * SEQ;
    const int col  = h * HDIM;
    const float scale = 0.08838834764831845f;   // 1/sqrt(128)

    // load Q tile (tf32-rounded)
    for (int i = tid; i < QT * HDIM / 4; i += 256) {
        int f = i * 4, r = f / HDIM, c = f % HDIM;
        float4 v = *reinterpret_cast<const float4*>(
            &qkv[(size_t)(tokb + q0 + r) * QKV_N + col + c]);
        float* p = &Qs[r * QLD + c];
        p[0] = to_tf32(v.x); p[1] = to_tf32(v.y); p[2] = to_tf32(v.z); p[3] = to_tf32(v.w);
    }
    if (tid < QT) { row_m[tid] = -3.0e38f; row_l[tid] = 0.0f; }

    float o[8][4];
#pragma unroll
    for (int n = 0; n < 8; n++) { o[n][0] = o[n][1] = o[n][2] = o[n][3] = 0.f; }

    __syncthreads();

    for (int kt = 0; kt < SEQ / KT; kt++) {
        const int k0 = kt * KT;
        // ---- K tile ----
        for (int i = tid; i < KT * HDIM / 4; i += 256) {
            int f = i * 4, r = f / HDIM, c = f % HDIM;
            float4 v = *reinterpret_cast<const float4*>(
                &qkv[(size_t)(tokb + k0 + r) * QKV_N + HIDDEN + col + c]);
            float* p = &KVs[r * QLD + c];
            p[0] = to_tf32(v.x); p[1] = to_tf32(v.y); p[2] = to_tf32(v.z); p[3] = to_tf32(v.w);
        }
        __syncthreads();

        // ---- scores: 16x32 per warp, S = Q @ K^T ----
        float s4[4][4];
#pragma unroll
        for (int n = 0; n < 4; n++) s4[n][0] = s4[n][1] = s4[n][2] = s4[n][3] = 0.f;
#pragma unroll
        for (int kk = 0; kk < HDIM; kk += 8) {
            uint32_t a0 = __float_as_uint(Qs[(wq * 16 + lr) * QLD + kk + lc]);
            uint32_t a1 = __float_as_uint(Qs[(wq * 16 + lr + 8) * QLD + kk + lc]);
            uint32_t a2 = __float_as_uint(Qs[(wq * 16 + lr) * QLD + kk + lc + 4]);
            uint32_t a3 = __float_as_uint(Qs[(wq * 16 + lr + 8) * QLD + kk + lc + 4]);
#pragma unroll
            for (int n = 0; n < 4; n++) {
                int nb = wh * 32 + n * 8;
                uint32_t b0 = __float_as_uint(KVs[(nb + lr) * QLD + kk + lc]);
                uint32_t b1 = __float_as_uint(KVs[(nb + lr) * QLD + kk + lc + 4]);
                mma_m16n8k8(s4[n][0], s4[n][1], s4[n][2], s4[n][3], a0, a1, a2, a3, b0, b1);
            }
        }
        // scale + additive mask -> Ps
#pragma unroll
        for (int n = 0; n < 4; n++) {
            int cb = wh * 32 + n * 8 + lc * 2;
            float mk0 = mask[b * SEQ + k0 + cb];
            float mk1 = mask[b * SEQ + k0 + cb + 1];
            int r0 = wq * 16 + lr, r1 = r0 + 8;
            Ps[r0 * PLD + cb]     = s4[n][0] * scale + mk0;
            Ps[r0 * PLD + cb + 1] = s4[n][1] * scale + mk1;
            Ps[r1 * PLD + cb]     = s4[n][2] * scale + mk0;
            Ps[r1 * PLD + cb + 1] = s4[n][3] * scale + mk1;
        }
        __syncthreads();

        // ---- online softmax: 4 threads per row ----
        {
            const int g = tid >> 2, lg = tid & 3;
            float mx = -3.0e38f;
#pragma unroll
            for (int j = 0; j < 16; j++) mx = fmaxf(mx, Ps[g * PLD + lg + j * 4]);
            mx = fmaxf(mx, __shfl_xor_sync(0xffffffffu, mx, 1));
            mx = fmaxf(mx, __shfl_xor_sync(0xffffffffu, mx, 2));
            float mold = row_m[g];
            float mnew = fmaxf(mold, mx);
            float corr = __expf(mold - mnew);
            float sum = 0.f;
#pragma unroll
            for (int j = 0; j < 16; j++) {
                float p = __expf(Ps[g * PLD + lg + j * 4] - mnew);
                sum += p;
                Ps[g * PLD + lg + j * 4] = to_tf32(p);
            }
            sum += __shfl_xor_sync(0xffffffffu, sum, 1);
            sum += __shfl_xor_sync(0xffffffffu, sum, 2);
            if (lg == 0) { row_l[g] = row_l[g] * corr + sum; row_m[g] = mnew; row_c[g] = corr; }
        }
        __syncthreads();

        // ---- rescale O accumulators by row correction ----
        {
            float c0 = row_c[wq * 16 + lr], c1 = row_c[wq * 16 + lr + 8];
#pragma unroll
            for (int n = 0; n < 8; n++) {
                o[n][0] *= c0; o[n][1] *= c0; o[n][2] *= c1; o[n][3] *= c1;
            }
        }
        // ---- V tile (reuse KVs) ----
        for (int i = tid; i < KT * HDIM / 4; i += 256) {
            int f = i * 4, r = f / HDIM, c = f % HDIM;
            float4 v = *reinterpret_cast<const float4*>(
                &qkv[(size_t)(tokb + k0 + r) * QKV_N + 2 * HIDDEN + col + c]);
            float* p = &KVs[r * QLD + c];
            p[0] = to_tf32(v.x); p[1] = to_tf32(v.y); p[2] = to_tf32(v.z); p[3] = to_tf32(v.w);
        }
        __syncthreads();

        // ---- PV: O += P @ V, 16x64 per warp ----
#pragma unroll
        for (int kk = 0; kk < KT; kk += 8) {
            uint32_t a0 = __float_as_uint(Ps[(wq * 16 + lr) * PLD + kk + lc]);
            uint32_t a1 = __float_as_uint(Ps[(wq * 16 + lr + 8) * PLD + kk + lc]);
            uint32_t a2 = __float_as_uint(Ps[(wq * 16 + lr) * PLD + kk + lc + 4]);
            uint32_t a3 = __float_as_uint(Ps[(wq * 16 + lr + 8) * PLD + kk + lc + 4]);
#pragma unroll
            for (int n = 0; n < 8; n++) {
                int nb = wh * 64 + n * 8;
                uint32_t b0 = __float_as_uint(KVs[(kk + lc) * QLD + nb + lr]);
                uint32_t b1 = __float_as_uint(KVs[(kk + lc + 4) * QLD + nb + lr]);
                mma_m16n8k8(o[n][0], o[n][1], o[n][2], o[n][3], a0, a1, a2, a3, b0, b1);
            }
        }
        __syncthreads();
    }

    // ---- finalize: divide by l, write ctx[token, h*128+d] ----
    {
        float inv0 = 1.f / row_l[wq * 16 + lr];
        float inv1 = 1.f / row_l[wq * 16 + lr + 8];
        int t0 = tokb + q0 + wq * 16 + lr;
#pragma unroll
        for (int n = 0; n < 8; n++) {
            int cb = wh * 64 + n * 8 + lc * 2;
            ctx[(size_t)t0 * HIDDEN + col + cb]           = o[n][0] * inv0;
            ctx[(size_t)t0 * HIDDEN + col + cb + 1]       = o[n][1] * inv0;
            ctx[(size_t)(t0 + 8) * HIDDEN + col + cb]     = o[n][2] * inv1;
            ctx[(size_t)(t0 + 8) * HIDDEN + col + cb + 1] = o[n][3] * inv1;
        }
    }
}

// ============================================================================
// Launch: QKV GEMM -> attention -> output GEMM. All graph-capturable.
// ============================================================================
extern "C" void kernel_launch(void* const* d_in, const int* in_sizes, int n_in,
                              void* d_out, int out_size)
{
    const float* hidden = (const float*)d_in[0];
    const float* mask   = (const float*)d_in[1];
    const float* Wqkv   = (const float*)d_in[2];
    const float* bqkv   = (const float*)d_in[3];
    const float* Wout   = (const float*)d_in[4];
    const float* bout   = (const float*)d_in[5];
    float* out = (float*)d_out;

    float* qkv = nullptr;
    float* ctx = nullptr;
    cudaGetSymbolAddress((void**)&qkv, g_qkv);
    cudaGetSymbolAddress((void**)&ctx, g_ctx);

    dim3 blk(256);

    // 1) QKV projection: [4096,2048] @ [2048,6144] + b_qkv
    gemm_bias_tf32<<<dim3(QKV_N / BN, TOKENS / BM), blk>>>(
        hidden, Wqkv, bqkv, qkv, TOKENS, QKV_N, HIDDEN);

    // 2) Attention
    size_t smem = (size_t)(2 * QT * QLD + QT * PLD + 3 * QT) * sizeof(float);  // ~86 KB
    cudaFuncSetAttribute(attn_tf32, cudaFuncAttributeMaxDynamicSharedMemorySize, (int)smem);
    attn_tf32<<<dim3(SEQ / QT, BATCH * NHEADS), blk, smem>>>(qkv, mask, ctx);

    // 3) Output projection: [4096,2048] @ [2048,2048] + b_out
    gemm_bias_tf32<<<dim3(HIDDEN / BN, TOKENS / BM), blk>>>(
        ctx, Wout, bout, out, TOKENS, HIDDEN, HIDDEN);
}

// round 2
// speedup vs baseline: 1.3105x; 1.3105x over previous
#include <cuda_runtime.h>
#include <mma.h>
#include <cstdint>

using namespace nvcuda;

#define HIDDEN 2048
#define NHEADS 16
#define HDIM   128
#define BATCH  2
#define SEQ    2048
#define TOKENS (BATCH * SEQ)     // 4096
#define QKV_N  (3 * HIDDEN)      // 6144

// Scratch (allocation-free rule: __device__ globals)
__device__ float g_qkv[(size_t)TOKENS * QKV_N];   // 96 MB
__device__ float g_ctx[(size_t)TOKENS * HIDDEN];  // 32 MB

__device__ __forceinline__ float to_tf32(float x) {
    uint32_t u;
    asm("cvt.rna.tf32.f32 %0, %1;" : "=r"(u) : "f"(x));
    return __uint_as_float(u);
}

__device__ __forceinline__ void cp_async16(void* smem, const void* gmem) {
    uint32_t s = (uint32_t)__cvta_generic_to_shared(smem);
    asm volatile("cp.async.cg.shared.global [%0], [%1], 16;" :: "r"(s), "l"(gmem));
}
__device__ __forceinline__ void cp_commit() {
    asm volatile("cp.async.commit_group;");
}
template <int N>
__device__ __forceinline__ void cp_wait() {
    asm volatile("cp.async.wait_group %0;" :: "n"(N));
}

__device__ __forceinline__ void mma_m16n8k8(float& c0, float& c1, float& c2, float& c3,
                                            uint32_t a0, uint32_t a1, uint32_t a2, uint32_t a3,
                                            uint32_t b0, uint32_t b1) {
    asm volatile(
        "mma.sync.aligned.m16n8k8.row.col.f32.tf32.tf32.f32 "
        "{%0,%1,%2,%3}, {%4,%5,%6,%7}, {%8,%9}, {%0,%1,%2,%3};\n"
        : "+f"(c0), "+f"(c1), "+f"(c2), "+f"(c3)
        : "r"(a0), "r"(a1), "r"(a2), "r"(a3), "r"(b0), "r"(b1));
}

// ============================================================================
// TF32 GEMM + fused bias, cp.async double-buffered.
// C[M,N] = A[M,K] @ B[K,N] + bias[N]
// Block tile 128x128, BK=32, 2 smem stages, 8 warps (2x4), warp tile 64x32.
// ============================================================================
#define BM 128
#define BN 128
#define BK 32
#define ALD 36    // As row stride (floats)
#define BLD 132   // Bs row stride (floats)
#define GEMM_SMEM ((2 * BM * ALD + 2 * BK * BLD + 16 * BLD) * 4)

__global__ __launch_bounds__(256, 2) void gemm_bias_tf32(
    const float* __restrict__ A, const float* __restrict__ B,
    const float* __restrict__ bias, float* __restrict__ C,
    int M, int N, int K)
{
    extern __shared__ float smg[];
    float* As   = smg;                    // 2 x 128 x 36
    float* Bs   = As + 2 * BM * ALD;      // 2 x 32 x 132
    float* Brep = Bs + 2 * BK * BLD;      // 16 x 132 (bias replicated)

    const int tid  = threadIdx.x;
    const int warp = tid >> 5;
    const int wr   = warp >> 2;   // 0..1
    const int wc   = warp & 3;    // 0..3
    const int row0 = blockIdx.y * BM;
    const int col0 = blockIdx.x * BN;

    // bias replicated over 16 rows (plain stores)
    for (int i = tid; i < 16 * BN; i += 256) {
        int r = i >> 7, c = i & 127;
        Brep[r * BLD + c] = bias[col0 + c];
    }

    // prologue: issue stages 0 and 1
#pragma unroll
    for (int st = 0; st < 2; st++) {
        const int k0 = st * BK;
        float* as = As + st * BM * ALD;
        float* bs = Bs + st * BK * BLD;
#pragma unroll
        for (int i = 0; i < 4; i++) {              // A: 128x32 floats = 1024 float4
            int idx = tid + i * 256;
            int r = idx >> 3, c4 = idx & 7;
            cp_async16(&as[r * ALD + c4 * 4], &A[(size_t)(row0 + r) * K + k0 + c4 * 4]);
        }
#pragma unroll
        for (int i = 0; i < 4; i++) {              // B: 32x128 floats = 1024 float4
            int idx = tid + i * 256;
            int r = idx >> 5, c4 = idx & 31;
            cp_async16(&bs[r * BLD + c4 * 4], &B[(size_t)(k0 + r) * N + col0 + c4 * 4]);
        }
        cp_commit();
    }

    __syncthreads();   // Brep visible

    wmma::fragment<wmma::accumulator, 16, 16, 8, float> acc[4][2];
#pragma unroll
    for (int i = 0; i < 4; i++)
#pragma unroll
        for (int j = 0; j < 2; j++)
            wmma::load_matrix_sync(acc[i][j], &Brep[wc * 32 + j * 16], BLD,
                                   wmma::mem_row_major);

    const int NKT = K / BK;
    for (int kt = 0; kt < NKT; kt++) {
        cp_wait<1>();
        __syncthreads();                       // stage p fully landed for all threads
        const int p = kt & 1;
        const float* as = As + p * BM * ALD;
        const float* bs = Bs + p * BK * BLD;

#pragma unroll
        for (int kk = 0; kk < BK; kk += 8) {
            wmma::fragment<wmma::matrix_a, 16, 16, 8, wmma::precision::tf32, wmma::row_major> fa[4];
            wmma::fragment<wmma::matrix_b, 16, 16, 8, wmma::precision::tf32, wmma::row_major> fb[2];
#pragma unroll
            for (int i = 0; i < 4; i++) {
                wmma::load_matrix_sync(fa[i], &as[(wr * 64 + i * 16) * ALD + kk], ALD);
#pragma unroll
                for (int t = 0; t < fa[i].num_elements; t++)
                    fa[i].x[t] = to_tf32(fa[i].x[t]);
            }
#pragma unroll
            for (int j = 0; j < 2; j++) {
                wmma::load_matrix_sync(fb[j], &bs[kk * BLD + wc * 32 + j * 16], BLD);
#pragma unroll
                for (int t = 0; t < fb[j].num_elements; t++)
                    fb[j].x[t] = to_tf32(fb[j].x[t]);
            }
#pragma unroll
            for (int i = 0; i < 4; i++)
#pragma unroll
                for (int j = 0; j < 2; j++)
                    wmma::mma_sync(acc[i][j], fa[i], fb[j], acc[i][j]);
        }
        __syncthreads();                       // all warps done reading stage p

        if (kt + 2 < NKT) {
            const int k0 = (kt + 2) * BK;
            float* asw = As + p * BM * ALD;
            float* bsw = Bs + p * BK * BLD;
#pragma unroll
            for (int i = 0; i < 4; i++) {
                int idx = tid + i * 256;
                int r = idx >> 3, c4 = idx & 7;
                cp_async16(&asw[r * ALD + c4 * 4], &A[(size_t)(row0 + r) * K + k0 + c4 * 4]);
            }
#pragma unroll
            for (int i = 0; i < 4; i++) {
                int idx = tid + i * 256;
                int r = idx >> 5, c4 = idx & 31;
                cp_async16(&bsw[r * BLD + c4 * 4], &B[(size_t)(k0 + r) * N + col0 + c4 * 4]);
            }
        }
        cp_commit();                           // commit (possibly empty) keeps group count aligned
    }

#pragma unroll
    for (int i = 0; i < 4; i++)
#pragma unroll
        for (int j = 0; j < 2; j++)
            wmma::store_matrix_sync(
                &C[(size_t)(row0 + wr * 64 + i * 16) * N + col0 + wc * 32 + j * 16],
                acc[i][j], N, wmma::mem_row_major);
}

// ============================================================================
// Flash attention, TF32 mma.sync, register-resident online softmax.
// Q-tile = 128 (8 warps x 16 q-rows), K-tile = 64, d = 128.
// Each warp computes ALL 64 k-cols of its 16 rows -> softmax reductions are
// 4-lane shuffles, no cross-warp smem. P lives in a warp-private smem strip.
// cp.async: V-tile load overlaps QK^T, next K-tile load overlaps PV.
// 2 barriers per KV tile.
// ============================================================================
#define QT  128
#define KT  64
#define LDK 132   // stride for Qs/Ks/Vs (=4 mod 32: conflict-free quad reads)
#define LDP 68    // stride for P strips
#define ATTN_SMEM ((QT * LDK + 2 * KT * LDK + 8 * 16 * LDP + KT) * 4)

__global__ __launch_bounds__(256, 1) void attn_tf32(
    const float* __restrict__ qkv, const float* __restrict__ mask,
    float* __restrict__ ctx)
{
    extern __shared__ float sm[];
    float* Qs = sm;                     // QT x LDK
    float* Ks = Qs + QT * LDK;          // KT x LDK
    float* Vs = Ks + KT * LDK;          // KT x LDK
    float* Ps = Vs + KT * LDK;          // 8 warps x 16 x LDP
    float* Ms = Ps + 8 * 16 * LDP;      // KT mask values

    const int tid  = threadIdx.x;
    const int warp = tid >> 5, lane = tid & 31;
    const int lr = lane >> 2, lc = lane & 3;
    const int b  = blockIdx.y >> 4, h = blockIdx.y & 15;
    const int q0 = blockIdx.x * QT;
    const int tokb = b * SEQ;
    const int col  = h * HDIM;
    const float scale = 0.08838834764831845f;   // 1/sqrt(128)

    const float* gK = qkv + (size_t)tokb * QKV_N + HIDDEN + col;
    const float* gV = gK + HIDDEN;

    // prologue: issue K tile 0 (raw fp32; cvt at operand read)
#pragma unroll
    for (int i = 0; i < 8; i++) {          // 64x128 floats = 2048 float4
        int idx = tid + i * 256;
        int r = idx >> 5, c4 = idx & 31;
        cp_async16(&Ks[r * LDK + c4 * 4], gK + (size_t)r * QKV_N + c4 * 4);
    }
    cp_commit();

    // Q tile load + tf32 cvt (plain)
    for (int i = tid; i < QT * HDIM / 4; i += 256) {
        int f = i * 4, r = f >> 7, c = f & 127;
        float4 v = *reinterpret_cast<const float4*>(
            &qkv[(size_t)(tokb + q0 + r) * QKV_N + col + c]);
        float* p = &Qs[r * LDK + c];
        p[0] = to_tf32(v.x); p[1] = to_tf32(v.y); p[2] = to_tf32(v.z); p[3] = to_tf32(v.w);
    }

    float o[16][4];
#pragma unroll
    for (int n = 0; n < 16; n++) { o[n][0] = o[n][1] = o[n][2] = o[n][3] = 0.f; }
    float m0 = -1e30f, m1 = -1e30f, l0 = 0.f, l1 = 0.f;

    const float* Qb  = Qs + (warp * 16 + lr) * LDK;
    float*       Psw = Ps + warp * 16 * LDP;

    for (int kt = 0; kt < SEQ / KT; kt++) {
        const int k0 = kt * KT;
        // mask strip for this tile (plain store; visible after syncA)
        if (tid < KT) Ms[tid] = mask[b * SEQ + k0 + tid];

        cp_wait<0>();            // K tile landed
        __syncthreads();         // syncA: Ks+Ms visible; all warps done with old Vs

        // issue V tile (overlaps QK^T)
#pragma unroll
        for (int i = 0; i < 8; i++) {
            int idx = tid + i * 256;
            int r = idx >> 5, c4 = idx & 31;
            cp_async16(&Vs[r * LDK + c4 * 4], gV + (size_t)(k0 + r) * QKV_N + c4 * 4);
        }
        cp_commit();

        // ---- S = Q @ K^T : 16 rows x 64 cols per warp ----
        float s[8][4];
#pragma unroll
        for (int n = 0; n < 8; n++) s[n][0] = s[n][1] = s[n][2] = s[n][3] = 0.f;
#pragma unroll
        for (int kk = 0; kk < HDIM; kk += 8) {
            uint32_t a0 = __float_as_uint(Qb[kk + lc]);
            uint32_t a1 = __float_as_uint(Qb[8 * LDK + kk + lc]);
            uint32_t a2 = __float_as_uint(Qb[kk + lc + 4]);
            uint32_t a3 = __float_as_uint(Qb[8 * LDK + kk + lc + 4]);
#pragma unroll
            for (int n = 0; n < 8; n++) {
                uint32_t b0 = __float_as_uint(to_tf32(Ks[(n * 8 + lr) * LDK + kk + lc]));
                uint32_t b1 = __float_as_uint(to_tf32(Ks[(n * 8 + lr) * LDK + kk + lc + 4]));
                mma_m16n8k8(s[n][0], s[n][1], s[n][2], s[n][3], a0, a1, a2, a3, b0, b1);
            }
        }

        // ---- register-resident online softmax (rows lr and lr+8) ----
        float mx0 = -1e30f, mx1 = -1e30f;
#pragma unroll
        for (int n = 0; n < 8; n++) {
            float mk0 = Ms[n * 8 + 2 * lc], mk1 = Ms[n * 8 + 2 * lc + 1];
            s[n][0] = s[n][0] * scale + mk0;
            s[n][1] = s[n][1] * scale + mk1;
            s[n][2] = s[n][2] * scale + mk0;
            s[n][3] = s[n][3] * scale + mk1;
            mx0 = fmaxf(mx0, fmaxf(s[n][0], s[n][1]));
            mx1 = fmaxf(mx1, fmaxf(s[n][2], s[n][3]));
        }
        mx0 = fmaxf(mx0, __shfl_xor_sync(0xffffffffu, mx0, 1));
        mx0 = fmaxf(mx0, __shfl_xor_sync(0xffffffffu, mx0, 2));
        mx1 = fmaxf(mx1, __shfl_xor_sync(0xffffffffu, mx1, 1));
        mx1 = fmaxf(mx1, __shfl_xor_sync(0xffffffffu, mx1, 2));
        float mn0 = fmaxf(m0, mx0), mn1 = fmaxf(m1, mx1);
        float c0 = __expf(m0 - mn0), c1 = __expf(m1 - mn1);
        m0 = mn0; m1 = mn1;
        float s0 = 0.f, s1 = 0.f;
#pragma unroll
        for (int n = 0; n < 8; n++) {
            float p00 = __expf(s[n][0] - mn0), p01 = __expf(s[n][1] - mn0);
            float p10 = __expf(s[n][2] - mn1), p11 = __expf(s[n][3] - mn1);
            s0 += p00 + p01;  s1 += p10 + p11;
            int cb = n * 8 + 2 * lc;
            Psw[lr * LDP + cb]           = to_tf32(p00);
            Psw[lr * LDP + cb + 1]       = to_tf32(p01);
            Psw[(lr + 8) * LDP + cb]     = to_tf32(p10);
            Psw[(lr + 8) * LDP + cb + 1] = to_tf32(p11);
        }
        s0 += __shfl_xor_sync(0xffffffffu, s0, 1);
        s0 += __shfl_xor_sync(0xffffffffu, s0, 2);
        s1 += __shfl_xor_sync(0xffffffffu, s1, 1);
        s1 += __shfl_xor_sync(0xffffffffu, s1, 2);
        l0 = l0 * c0 + s0;
        l1 = l1 * c1 + s1;
#pragma unroll
        for (int n = 0; n < 16; n++) {
            o[n][0] *= c0; o[n][1] *= c0; o[n][2] *= c1; o[n][3] *= c1;
        }

        cp_wait<0>();            // V tile landed
        __syncthreads();         // syncB: Vs visible; all warps done reading Ks; P visible

        // issue next K tile (overlaps PV)
        if (kt + 1 < SEQ / KT) {
#pragma unroll
            for (int i = 0; i < 8; i++) {
                int idx = tid + i * 256;
                int r = idx >> 5, c4 = idx & 31;
                cp_async16(&Ks[r * LDK + c4 * 4],
                           gK + (size_t)(k0 + KT + r) * QKV_N + c4 * 4);
            }
        }
        cp_commit();

        // ---- O += P @ V : 16 rows x 128 d-cols per warp ----
#pragma unroll
        for (int kk = 0; kk < KT; kk += 8) {
            uint32_t a0 = __float_as_uint(Psw[lr * LDP + kk + lc]);
            uint32_t a1 = __float_as_uint(Psw[(lr + 8) * LDP + kk + lc]);
            uint32_t a2 = __float_as_uint(Psw[lr * LDP + kk + lc + 4]);
            uint32_t a3 = __float_as_uint(Psw[(lr + 8) * LDP + kk + lc + 4]);
#pragma unroll
            for (int n = 0; n < 16; n++) {
                uint32_t b0 = __float_as_uint(to_tf32(Vs[(kk + lc) * LDK + n * 8 + lr]));
                uint32_t b1 = __float_as_uint(to_tf32(Vs[(kk + lc + 4) * LDK + n * 8 + lr]));
                mma_m16n8k8(o[n][0], o[n][1], o[n][2], o[n][3], a0, a1, a2, a3, b0, b1);
            }
        }
    }

    // ---- finalize ----
    float inv0 = 1.f / l0, inv1 = 1.f / l1;
    int t0 = tokb + q0 + warp * 16 + lr;
#pragma unroll
    for (int n = 0; n < 16; n++) {
        int cb = n * 8 + 2 * lc;
        ctx[(size_t)t0 * HIDDEN + col + cb]           = o[n][0] * inv0;
        ctx[(size_t)t0 * HIDDEN + col + cb + 1]       = o[n][1] * inv0;
        ctx[(size_t)(t0 + 8) * HIDDEN + col + cb]     = o[n][2] * inv1;
        ctx[(size_t)(t0 + 8) * HIDDEN + col + cb + 1] = o[n][3] * inv1;
    }
}

// ============================================================================
// Launch: QKV GEMM -> attention -> output GEMM. All graph-capturable.
// ============================================================================
extern "C" void kernel_launch(void* const* d_in, const int* in_sizes, int n_in,
                              void* d_out, int out_size)
{
    const float* hidden = (const float*)d_in[0];
    const float* mask   = (const float*)d_in[1];
    const float* Wqkv   = (const float*)d_in[2];
    const float* bqkv   = (const float*)d_in[3];
    const float* Wout   = (const float*)d_in[4];
    const float* bout   = (const float*)d_in[5];
    float* out = (float*)d_out;

    float* qkv = nullptr;
    float* ctx = nullptr;
    cudaGetSymbolAddress((void**)&qkv, g_qkv);
    cudaGetSymbolAddress((void**)&ctx, g_ctx);

    dim3 blk(256);

    cudaFuncSetAttribute(gemm_bias_tf32,
                         cudaFuncAttributeMaxDynamicSharedMemorySize, GEMM_SMEM);
    cudaFuncSetAttribute(attn_tf32,
                         cudaFuncAttributeMaxDynamicSharedMemorySize, ATTN_SMEM);

    // 1) QKV projection: [4096,2048] @ [2048,6144] + b_qkv
    gemm_bias_tf32<<<dim3(QKV_N / BN, TOKENS / BM), blk, GEMM_SMEM>>>(
        hidden, Wqkv, bqkv, qkv, TOKENS, QKV_N, HIDDEN);

    // 2) Attention
    attn_tf32<<<dim3(SEQ / QT, BATCH * NHEADS), blk, ATTN_SMEM>>>(qkv, mask, ctx);

    // 3) Output projection: [4096,2048] @ [2048,2048] + b_out
    gemm_bias_tf32<<<dim3(HIDDEN / BN, TOKENS / BM), blk, GEMM_SMEM>>>(
        ctx, Wout, bout, out, TOKENS, HIDDEN, HIDDEN);
}